// round 5
// baseline (speedup 1.0000x reference)
#include <cuda_runtime.h>
#include <cuda_bf16.h>
#include <cstdint>

#define N_NODES   10000
#define N_EDGES   160000
#define E_TOT     170000      // edges + self loops
#define IN_CH     4097
#define HID       512
#define HEADS     4
#define C1        2048        // HEADS*HID
#define OUT_CH    256
#define N_GRAPHS  64
#define NEG_SLOPE 0.2f

// ---------------- scratch (device globals; no allocation allowed) ----------------
__device__ __align__(16) float g_h1[(size_t)N_NODES * C1];      // x @ W1
__device__ __align__(16) float g_o1[(size_t)N_NODES * C1];      // relu(gat1 out)
__device__ __align__(16) float g_h2[(size_t)N_NODES * OUT_CH];  // o1 @ W2
__device__ __align__(16) float g_as1[N_NODES * HEADS];
__device__ __align__(16) float g_ad1[N_NODES * HEADS];
__device__ __align__(16) float g_as2[N_NODES];
__device__ __align__(16) float g_ad2[N_NODES];
__device__ __align__(16) float g_w1[(size_t)E_TOT * HEADS];     // per-edge softmax numerators
__device__ __align__(16) float g_w2[E_TOT];
__device__ __align__(16) int   g_deg[N_NODES];
__device__ __align__(16) int   g_start[N_NODES + 1];
__device__ __align__(16) int   g_cursor[N_NODES];
__device__ __align__(16) int   g_eid[E_TOT];
__device__ __align__(16) float g_pool[N_GRAPHS * OUT_CH];
__device__ __align__(16) float g_cnt[N_GRAPHS];
__device__ int g_is64_ei;   // 1 if edge_index buffer is int64, 0 if int32
__device__ int g_is64_b;    // same for batch

// ---------------- dtype-robust, clamped index accessors ----------------
// Clamping guarantees no OOB anywhere downstream even if the dtype probe is
// wrong: a wrong guess then shows up as a large-but-finite rel_err (signal),
// not an IMA (no signal).
__device__ __forceinline__ int clampi(int v, int hi) {
    return v < 0 ? 0 : (v >= hi ? hi - 1 : v);
}
__device__ __forceinline__ int edge_src(const void* ei, int e) {
    if (e >= N_EDGES) return e - N_EDGES;                       // self loop
    int v = g_is64_ei ? (int)((const long long*)ei)[e]
                      : ((const int*)ei)[e];
    return clampi(v, N_NODES);
}
__device__ __forceinline__ int edge_dst(const void* ei, int e) {
    if (e >= N_EDGES) return e - N_EDGES;
    int v = g_is64_ei ? (int)((const long long*)ei)[N_EDGES + e]
                      : ((const int*)ei)[N_EDGES + e];
    return clampi(v, N_NODES);
}
__device__ __forceinline__ int batch_of(const void* b, int n) {
    int v = g_is64_b ? (int)((const long long*)b)[n]
                     : ((const int*)b)[n];
    return clampi(v, N_GRAPHS);
}

// Probe dtypes: view buffers as int32 words (safe: we read only n_elements words,
// which both layouts contain). Non-negative int64 values < 2^31 have all odd-
// indexed words == 0; genuine int32 data has nonzero odd words w.p. ~1.
__global__ void k_detect(const int* __restrict__ eiw, const int* __restrict__ bw) {
    __shared__ int s_ei, s_b;
    int t = threadIdx.x;
    if (t == 0) { s_ei = 0; s_b = 0; }
    __syncthreads();
    int le = 0, lb = 0;
    for (int i = 2 * t + 1; i < 2 * N_EDGES; i += 2048) le |= (eiw[i] != 0);
    for (int i = 2 * t + 1; i < N_NODES;     i += 2048) lb |= (bw[i]  != 0);
    if (le) atomicOr(&s_ei, 1);
    if (lb) atomicOr(&s_b, 1);
    __syncthreads();
    if (t == 0) { g_is64_ei = !s_ei; g_is64_b = !s_b; }
}

// ---------------- helpers ----------------
__device__ __forceinline__ float warp_max(float v) {
    #pragma unroll
    for (int o = 16; o; o >>= 1) v = fmaxf(v, __shfl_xor_sync(0xffffffffu, v, o));
    return v;
}
__device__ __forceinline__ float warp_sum(float v) {
    #pragma unroll
    for (int o = 16; o; o >>= 1) v += __shfl_xor_sync(0xffffffffu, v, o);
    return v;
}
__device__ __forceinline__ unsigned f2tf32(float v) {
    unsigned u;
    asm("cvt.rna.tf32.f32 %0, %1;" : "=r"(u) : "f"(v));
    return u;
}
__device__ __forceinline__ void mma_tf32(float* c, const unsigned* a, const unsigned* b) {
    asm volatile(
        "mma.sync.aligned.m16n8k8.row.col.f32.tf32.tf32.f32 "
        "{%0,%1,%2,%3},{%4,%5,%6,%7},{%8,%9},{%0,%1,%2,%3};"
        : "+f"(c[0]), "+f"(c[1]), "+f"(c[2]), "+f"(c[3])
        : "r"(a[0]), "r"(a[1]), "r"(a[2]), "r"(a[3]), "r"(b[0]), "r"(b[1]));
}
__device__ __forceinline__ void cpa4(uint32_t dst, const float* src, bool pred) {
    int sz = pred ? 4 : 0;
    asm volatile("cp.async.ca.shared.global [%0], [%1], 4, %2;"
                 :: "r"(dst), "l"(src), "r"(sz));
}
__device__ __forceinline__ void cpa16(uint32_t dst, const float* src, bool pred) {
    int sz = pred ? 16 : 0;
    asm volatile("cp.async.cg.shared.global [%0], [%1], 16, %2;"
                 :: "r"(dst), "l"(src), "r"(sz));
}
__device__ __forceinline__ void cpa_commit() {
    asm volatile("cp.async.commit_group;");
}
template <int N>
__device__ __forceinline__ void cpa_wait() {
    asm volatile("cp.async.wait_group %0;" :: "n"(N));
}

// ---------------- setup kernels ----------------
__global__ void k_zero() {
    int i = blockIdx.x * blockDim.x + threadIdx.x;
    if (i < N_NODES) g_deg[i] = 0;
    if (i < N_GRAPHS * OUT_CH) g_pool[i] = 0.f;
    if (i < N_GRAPHS) g_cnt[i] = 0.f;
}

__global__ void k_hist(const void* __restrict__ ei) {
    int e = blockIdx.x * blockDim.x + threadIdx.x;
    if (e >= E_TOT) return;
    atomicAdd(&g_deg[edge_dst(ei, e)], 1);
}

__global__ void k_prefix() {
    __shared__ int part[1024];
    int t = threadIdx.x;
    int s = 0;
    if (t < 1000) {
        #pragma unroll
        for (int i = 0; i < 10; i++) s += g_deg[t * 10 + i];
    }
    part[t] = s;
    __syncthreads();
    for (int off = 1; off < 1024; off <<= 1) {
        int v = (t >= off) ? part[t - off] : 0;
        __syncthreads();
        part[t] += v;
        __syncthreads();
    }
    if (t < 1000) {
        int run = part[t] - s;  // exclusive
        #pragma unroll
        for (int i = 0; i < 10; i++) {
            int d = g_deg[t * 10 + i];
            g_start[t * 10 + i]  = run;
            g_cursor[t * 10 + i] = run;
            run += d;
        }
    }
    if (t == 1023) g_start[N_NODES] = part[1023];
}

__global__ void k_scatter(const void* __restrict__ ei) {
    int e = blockIdx.x * blockDim.x + threadIdx.x;
    if (e >= E_TOT) return;
    int pos = atomicAdd(&g_cursor[edge_dst(ei, e)], 1);
    g_eid[pos] = e;
}

__global__ void k_cnt(const void* __restrict__ batch) {
    int n = blockIdx.x * blockDim.x + threadIdx.x;
    if (n < N_NODES) atomicAdd(&g_cnt[batch_of(batch, n)], 1.0f);
}

// ---------------- tf32 GEMM: C[M,N] = A[M,K] @ B[K,N], cp.async double-buffered --------
// which==0: A = x (param, K=4097 odd -> scalar cp.async), C = g_h1
// which==1: A = g_o1 (K=2048 -> vector cp.async),         C = g_h2
#define AS_STRIDE 36
#define BS_STRIDE 132
#define AS_SZ (128 * AS_STRIDE)     // 4608 floats
#define BS_SZ (32 * BS_STRIDE)      // 4224 floats
#define GEMM_SMEM_BYTES ((2 * AS_SZ + 2 * BS_SZ) * 4)   // 70656 B

__device__ __forceinline__ void load_tile(const float* __restrict__ A,
                                          const float* __restrict__ Bm,
                                          int M, int N, int K,
                                          int bm, int bn, int kt,
                                          float* As, float* Bs, int tid, bool aVec) {
    if (aVec) {
        // A rows 16B aligned: 4 x 16B per thread (128 rows x 8 float4)
        #pragma unroll
        for (int p = 0; p < 4; p++) {
            int idx = tid + p * 256;
            int r = idx >> 3, c4 = idx & 7;
            int gr = bm + r, gk = kt + c4 * 4;
            bool v = (gr < M) && (gk < K);
            uint32_t d = (uint32_t)__cvta_generic_to_shared(As + r * AS_STRIDE + c4 * 4);
            const float* s = v ? (A + (size_t)gr * K + gk) : A;
            cpa16(d, s, v);
        }
    } else {
        // odd K: 16 x 4B per thread
        #pragma unroll
        for (int p = 0; p < 16; p++) {
            int idx = tid + p * 256;
            int r = idx >> 5, kk = idx & 31;
            int gr = bm + r, gk = kt + kk;
            bool v = (gr < M) && (gk < K);
            uint32_t d = (uint32_t)__cvta_generic_to_shared(As + r * AS_STRIDE + kk);
            const float* s = v ? (A + (size_t)gr * K + gk) : A;
            cpa4(d, s, v);
        }
    }
    // B: 4 x 16B per thread (32 rows x 32 float4)
    #pragma unroll
    for (int p = 0; p < 4; p++) {
        int idx = tid + p * 256;
        int r = idx >> 5, c4 = idx & 31;
        int gk = kt + r;
        bool v = (gk < K);
        uint32_t d = (uint32_t)__cvta_generic_to_shared(Bs + r * BS_STRIDE + c4 * 4);
        const float* s = v ? (Bm + (size_t)gk * N + bn + c4 * 4) : Bm;
        cpa16(d, s, v);
    }
}

__device__ __forceinline__ void cvt_tile(float* As, float* Bs, int tid) {
    #pragma unroll
    for (int p = 0; p < 16; p++) {
        int idx = tid + p * 256;
        float* a = As + (idx >> 5) * AS_STRIDE + (idx & 31);
        *a = __uint_as_float(f2tf32(*a));
    }
    #pragma unroll
    for (int p = 0; p < 4; p++) {
        int idx = tid + p * 256;
        float* b = Bs + (idx >> 5) * BS_STRIDE + (idx & 31) * 4;
        float4 v = *(float4*)b;
        v.x = __uint_as_float(f2tf32(v.x));
        v.y = __uint_as_float(f2tf32(v.y));
        v.z = __uint_as_float(f2tf32(v.z));
        v.w = __uint_as_float(f2tf32(v.w));
        *(float4*)b = v;
    }
}

__global__ __launch_bounds__(256, 2)
void k_gemm_tf32(int which, const float* __restrict__ Aext,
                 const float* __restrict__ B, int M, int N, int K) {
    extern __shared__ float sm[];
    float* AsBuf[2] = { sm,               sm + AS_SZ };
    float* BsBuf[2] = { sm + 2 * AS_SZ,   sm + 2 * AS_SZ + BS_SZ };

    const float* A = (which == 0) ? Aext : g_o1;
    float* C = (which == 0) ? g_h1 : g_h2;
    const bool aVec = (which != 0);

    int tid = threadIdx.x;
    int wid = tid >> 5, lane = tid & 31;
    int wm = wid & 3, wn = wid >> 2;       // warps 4 x 2 over 128x128
    int bm = blockIdx.x * 128, bn = blockIdx.y * 128;

    float c[2][8][4];
    #pragma unroll
    for (int i = 0; i < 2; i++)
        #pragma unroll
        for (int j = 0; j < 8; j++)
            #pragma unroll
            for (int q = 0; q < 4; q++) c[i][j][q] = 0.f;

    const int nt = (K + 31) / 32;
    load_tile(A, B, M, N, K, bm, bn, 0, AsBuf[0], BsBuf[0], tid, aVec);
    cpa_commit();

    for (int t = 0; t < nt; t++) {
        int cur = t & 1;
        if (t + 1 < nt) {
            load_tile(A, B, M, N, K, bm, bn, (t + 1) * 32,
                      AsBuf[cur ^ 1], BsBuf[cur ^ 1], tid, aVec);
            cpa_commit();
            cpa_wait<1>();
        } else {
            cpa_wait<0>();
        }
        __syncthreads();
        cvt_tile(AsBuf[cur], BsBuf[cur], tid);
        __syncthreads();

        float* As32 = AsBuf[cur];
        float* Bs32 = BsBuf[cur];
        #pragma unroll
        for (int ks = 0; ks < 4; ks++) {
            int k0 = ks * 8;
            unsigned a[2][4], b[8][2];
            #pragma unroll
            for (int mt = 0; mt < 2; mt++) {
                int r0 = wm * 32 + mt * 16 + (lane >> 2);
                int c0 = k0 + (lane & 3);
                a[mt][0] = __float_as_uint(As32[r0 * AS_STRIDE + c0]);
                a[mt][1] = __float_as_uint(As32[(r0 + 8) * AS_STRIDE + c0]);
                a[mt][2] = __float_as_uint(As32[r0 * AS_STRIDE + c0 + 4]);
                a[mt][3] = __float_as_uint(As32[(r0 + 8) * AS_STRIDE + c0 + 4]);
            }
            #pragma unroll
            for (int nt2 = 0; nt2 < 8; nt2++) {
                int kb = k0 + (lane & 3);
                int nb = wn * 64 + nt2 * 8 + (lane >> 2);
                b[nt2][0] = __float_as_uint(Bs32[kb * BS_STRIDE + nb]);
                b[nt2][1] = __float_as_uint(Bs32[(kb + 4) * BS_STRIDE + nb]);
            }
            #pragma unroll
            for (int mt = 0; mt < 2; mt++)
                #pragma unroll
                for (int nt2 = 0; nt2 < 8; nt2++)
                    mma_tf32(c[mt][nt2], a[mt], b[nt2]);
        }
        __syncthreads();   // protect buffer `cur` from the t+2 prefetch
    }

    // epilogue
    #pragma unroll
    for (int mt = 0; mt < 2; mt++) {
        int r0 = bm + wm * 32 + mt * 16 + (lane >> 2);
        #pragma unroll
        for (int nt2 = 0; nt2 < 8; nt2++) {
            int cc = bn + wn * 64 + nt2 * 8 + (lane & 3) * 2;
            if (r0 < M) {
                C[(size_t)r0 * N + cc]     = c[mt][nt2][0];
                C[(size_t)r0 * N + cc + 1] = c[mt][nt2][1];
            }
            if (r0 + 8 < M) {
                C[(size_t)(r0 + 8) * N + cc]     = c[mt][nt2][2];
                C[(size_t)(r0 + 8) * N + cc + 1] = c[mt][nt2][3];
            }
        }
    }
}

// ---------------- attention dot products ----------------
__global__ void k_att1(const float* __restrict__ att_s, const float* __restrict__ att_d) {
    int n = blockIdx.x;
    int h = threadIdx.x >> 5, lane = threadIdx.x & 31;
    const float* row = g_h1 + (size_t)n * C1 + h * HID;
    float ss = 0.f, sd = 0.f;
    #pragma unroll 4
    for (int ch = lane; ch < HID; ch += 32) {
        float v = row[ch];
        ss += v * att_s[h * HID + ch];
        sd += v * att_d[h * HID + ch];
    }
    ss = warp_sum(ss);
    sd = warp_sum(sd);
    if (!lane) { g_as1[n * HEADS + h] = ss; g_ad1[n * HEADS + h] = sd; }
}

__global__ void k_att2(const float* __restrict__ att_s, const float* __restrict__ att_d) {
    int wid = threadIdx.x >> 5, lane = threadIdx.x & 31;
    int n = blockIdx.x * 4 + wid;
    if (n >= N_NODES) return;
    const float* row = g_h2 + (size_t)n * OUT_CH;
    float ss = 0.f, sd = 0.f;
    #pragma unroll
    for (int ch = lane; ch < OUT_CH; ch += 32) {
        float v = row[ch];
        ss += v * att_s[ch];
        sd += v * att_d[ch];
    }
    ss = warp_sum(ss);
    sd = warp_sum(sd);
    if (!lane) { g_as2[n] = ss; g_ad2[n] = sd; }
}

// ---------------- layer-1 fused softmax + aggregation (no atomics) ----------------
__global__ __launch_bounds__(256)
void k_agg1(const void* __restrict__ ei, const float* __restrict__ b1) {
    __shared__ float sred[8][4];
    int n = blockIdx.x, tid = threadIdx.x;
    int wid = tid >> 5, lane = tid & 31;
    int s0 = g_start[n], s1 = g_start[n + 1];

    const float4 ad = *(const float4*)(g_ad1 + n * 4);

    // phase A: per-head max over incoming edges
    float m0 = -3.0e38f, m1 = m0, m2 = m0, m3 = m0;
    for (int j = s0 + tid; j < s1; j += 256) {
        int src = edge_src(ei, g_eid[j]);
        const float4 as = *(const float4*)(g_as1 + src * 4);
        float l;
        l = as.x + ad.x; l = l > 0.f ? l : NEG_SLOPE * l; m0 = fmaxf(m0, l);
        l = as.y + ad.y; l = l > 0.f ? l : NEG_SLOPE * l; m1 = fmaxf(m1, l);
        l = as.z + ad.z; l = l > 0.f ? l : NEG_SLOPE * l; m2 = fmaxf(m2, l);
        l = as.w + ad.w; l = l > 0.f ? l : NEG_SLOPE * l; m3 = fmaxf(m3, l);
    }
    m0 = warp_max(m0); m1 = warp_max(m1); m2 = warp_max(m2); m3 = warp_max(m3);
    if (!lane) { sred[wid][0] = m0; sred[wid][1] = m1; sred[wid][2] = m2; sred[wid][3] = m3; }
    __syncthreads();
    float fm0 = sred[0][0], fm1 = sred[0][1], fm2 = sred[0][2], fm3 = sred[0][3];
    #pragma unroll
    for (int w = 1; w < 8; w++) {
        fm0 = fmaxf(fm0, sred[w][0]); fm1 = fmaxf(fm1, sred[w][1]);
        fm2 = fmaxf(fm2, sred[w][2]); fm3 = fmaxf(fm3, sred[w][3]);
    }
    __syncthreads();

    // phase B: exp + denominator, store numerators in CSR order
    float d0 = 0.f, d1 = 0.f, d2 = 0.f, d3 = 0.f;
    for (int j = s0 + tid; j < s1; j += 256) {
        int src = edge_src(ei, g_eid[j]);
        const float4 as = *(const float4*)(g_as1 + src * 4);
        float l; float4 w;
        l = as.x + ad.x; l = l > 0.f ? l : NEG_SLOPE * l; w.x = __expf(l - fm0);
        l = as.y + ad.y; l = l > 0.f ? l : NEG_SLOPE * l; w.y = __expf(l - fm1);
        l = as.z + ad.z; l = l > 0.f ? l : NEG_SLOPE * l; w.z = __expf(l - fm2);
        l = as.w + ad.w; l = l > 0.f ? l : NEG_SLOPE * l; w.w = __expf(l - fm3);
        *(float4*)(g_w1 + (size_t)j * 4) = w;
        d0 += w.x; d1 += w.y; d2 += w.z; d3 += w.w;
    }
    d0 = warp_sum(d0); d1 = warp_sum(d1); d2 = warp_sum(d2); d3 = warp_sum(d3);
    if (!lane) { sred[wid][0] = d0; sred[wid][1] = d1; sred[wid][2] = d2; sred[wid][3] = d3; }
    __syncthreads();
    float fd0 = 0.f, fd1 = 0.f, fd2 = 0.f, fd3 = 0.f;
    #pragma unroll
    for (int w = 0; w < 8; w++) {
        fd0 += sred[w][0]; fd1 += sred[w][1]; fd2 += sred[w][2]; fd3 += sred[w][3];
    }
    __syncthreads();   // also makes g_w1 writes visible to all threads in block

    // phase C: weighted gather-accumulate. thread owns ch [tid*4, tid*4+4) and +1024.
    int ha = tid >> 7;        // head of first group (0 or 1); second group head = ha+2
    float inva = 1.f / ((ha ? fd1 : fd0) + 1e-16f);
    float invb = 1.f / ((ha ? fd3 : fd2) + 1e-16f);
    float4 acc0 = {0.f, 0.f, 0.f, 0.f}, acc1 = {0.f, 0.f, 0.f, 0.f};
    int c0 = tid * 4, c1 = (tid + 256) * 4;
    for (int j = s0; j < s1; j++) {
        int src = edge_src(ei, g_eid[j]);     // broadcast across warp
        const float* hrow = g_h1 + (size_t)src * C1;
        float wa = g_w1[(size_t)j * 4 + ha];
        float wb = g_w1[(size_t)j * 4 + ha + 2];
        float4 v0 = *(const float4*)(hrow + c0);
        float4 v1 = *(const float4*)(hrow + c1);
        acc0.x += wa * v0.x; acc0.y += wa * v0.y; acc0.z += wa * v0.z; acc0.w += wa * v0.w;
        acc1.x += wb * v1.x; acc1.y += wb * v1.y; acc1.z += wb * v1.z; acc1.w += wb * v1.w;
    }
    float* out = g_o1 + (size_t)n * C1;
    float4 o0, o1;
    o0.x = fmaxf(acc0.x * inva + b1[c0 + 0], 0.f);
    o0.y = fmaxf(acc0.y * inva + b1[c0 + 1], 0.f);
    o0.z = fmaxf(acc0.z * inva + b1[c0 + 2], 0.f);
    o0.w = fmaxf(acc0.w * inva + b1[c0 + 3], 0.f);
    o1.x = fmaxf(acc1.x * invb + b1[c1 + 0], 0.f);
    o1.y = fmaxf(acc1.y * invb + b1[c1 + 1], 0.f);
    o1.z = fmaxf(acc1.z * invb + b1[c1 + 2], 0.f);
    o1.w = fmaxf(acc1.w * invb + b1[c1 + 3], 0.f);
    *(float4*)(out + c0) = o0;
    *(float4*)(out + c1) = o1;
}

// ---------------- layer-2 fused softmax + aggregation + pooling ----------------
__global__ __launch_bounds__(256)
void k_agg2(const void* __restrict__ ei, const float* __restrict__ b2,
            const void* __restrict__ batch) {
    __shared__ float sred[8];
    int n = blockIdx.x, tid = threadIdx.x;
    int wid = tid >> 5, lane = tid & 31;
    int s0 = g_start[n], s1 = g_start[n + 1];
    float adn = g_ad2[n];

    float mx = -3.0e38f;
    for (int j = s0 + tid; j < s1; j += 256) {
        int src = edge_src(ei, g_eid[j]);
        float l = g_as2[src] + adn;
        l = l > 0.f ? l : NEG_SLOPE * l;
        mx = fmaxf(mx, l);
    }
    mx = warp_max(mx);
    if (!lane) sred[wid] = mx;
    __syncthreads();
    float fmx = sred[0];
    #pragma unroll
    for (int w = 1; w < 8; w++) fmx = fmaxf(fmx, sred[w]);
    __syncthreads();

    float ds = 0.f;
    for (int j = s0 + tid; j < s1; j += 256) {
        int src = edge_src(ei, g_eid[j]);
        float l = g_as2[src] + adn;
        l = l > 0.f ? l : NEG_SLOPE * l;
        float w = __expf(l - fmx);
        g_w2[j] = w;
        ds += w;
    }
    ds = warp_sum(ds);
    if (!lane) sred[wid] = ds;
    __syncthreads();
    float fden = 0.f;
    #pragma unroll
    for (int w = 0; w < 8; w++) fden += sred[w];
    __syncthreads();   // g_w2 visible
    float inv = 1.f / (fden + 1e-16f);

    float acc = 0.f;
    for (int j = s0; j < s1; j++) {
        int src = edge_src(ei, g_eid[j]);
        acc += g_w2[j] * g_h2[(size_t)src * OUT_CH + tid];
    }
    float val = acc * inv + b2[tid];
    atomicAdd(&g_pool[batch_of(batch, n) * OUT_CH + tid], val);
}

__global__ void k_final(float* __restrict__ out) {
    int i = blockIdx.x * blockDim.x + threadIdx.x;
    if (i < N_GRAPHS * OUT_CH) {
        float c = g_cnt[i >> 8];
        out[i] = g_pool[i] / fmaxf(c, 1.0f);
    }
}

// ---------------- launch ----------------
extern "C" void kernel_launch(void* const* d_in, const int* in_sizes, int n_in,
                              void* d_out, int out_size) {
    const float* x     = (const float*)d_in[0];
    const void*  ei    = d_in[1];
    const void*  batch = d_in[2];
    const float* W1    = (const float*)d_in[3];
    const float* as1   = (const float*)d_in[4];
    const float* ad1   = (const float*)d_in[5];
    const float* b1    = (const float*)d_in[6];
    const float* W2    = (const float*)d_in[7];
    const float* as2   = (const float*)d_in[8];
    const float* ad2   = (const float*)d_in[9];
    const float* b2    = (const float*)d_in[10];
    float* out = (float*)d_out;

    cudaFuncSetAttribute(k_gemm_tf32,
                         cudaFuncAttributeMaxDynamicSharedMemorySize,
                         GEMM_SMEM_BYTES);

    k_detect<<<1, 1024>>>((const int*)ei, (const int*)batch);
    k_zero<<<64, 256>>>();
    k_hist<<<(E_TOT + 255) / 256, 256>>>(ei);
    k_prefix<<<1, 1024>>>();
    k_scatter<<<(E_TOT + 255) / 256, 256>>>(ei);
    k_cnt<<<(N_NODES + 255) / 256, 256>>>(batch);

    dim3 g1((N_NODES + 127) / 128, C1 / 128);
    k_gemm_tf32<<<g1, 256, GEMM_SMEM_BYTES>>>(0, x, W1, N_NODES, C1, IN_CH);

    k_att1<<<N_NODES, 128>>>(as1, ad1);
    k_agg1<<<N_NODES, 256>>>(ei, b1);

    dim3 g2((N_NODES + 127) / 128, OUT_CH / 128);
    k_gemm_tf32<<<g2, 256, GEMM_SMEM_BYTES>>>(1, nullptr, W2, N_NODES, OUT_CH, C1);

    k_att2<<<(N_NODES + 3) / 4, 128>>>(as2, ad2);
    k_agg2<<<N_NODES, 256>>>(ei, b2, batch);

    k_final<<<(N_GRAPHS * OUT_CH + 255) / 256, 256>>>(out);
}

// round 7
// speedup vs baseline: 1.3205x; 1.3205x over previous
#include <cuda_runtime.h>
#include <cuda_bf16.h>
#include <cstdint>

#define N_NODES   10000
#define N_EDGES   160000
#define E_TOT     170000      // edges + self loops
#define IN_CH     4097
#define HID       512
#define HEADS     4
#define C1        2048        // HEADS*HID
#define OUT_CH    256
#define N_GRAPHS  64
#define NEG_SLOPE 0.2f

// ---------------- scratch (device globals; no allocation allowed) ----------------
__device__ __align__(16) float g_h1[(size_t)N_NODES * C1];      // x @ W1
__device__ __align__(16) float g_o1[(size_t)N_NODES * C1];      // relu(gat1 out)
__device__ __align__(16) float g_h2[(size_t)N_NODES * OUT_CH];  // o1 @ W2
__device__ __align__(16) float g_as1[N_NODES * HEADS];
__device__ __align__(16) float g_ad1[N_NODES * HEADS];
__device__ __align__(16) float g_as2[N_NODES];
__device__ __align__(16) float g_ad2[N_NODES];
__device__ __align__(16) int   g_deg[N_NODES];
__device__ __align__(16) int   g_start[N_NODES + 1];
__device__ __align__(16) int   g_cursor[N_NODES];
__device__ __align__(16) int   g_eid[E_TOT];
__device__ __align__(16) float g_pool[N_GRAPHS * OUT_CH];
__device__ __align__(16) float g_cnt[N_GRAPHS];
__device__ int g_is64_ei;   // 1 if edge_index buffer is int64, 0 if int32
__device__ int g_is64_b;    // same for batch

// ---------------- dtype-robust, clamped index accessors ----------------
__device__ __forceinline__ int clampi(int v, int hi) {
    return v < 0 ? 0 : (v >= hi ? hi - 1 : v);
}
__device__ __forceinline__ int edge_src(const void* ei, int e) {
    if (e >= N_EDGES) return e - N_EDGES;                       // self loop
    int v = g_is64_ei ? (int)((const long long*)ei)[e]
                      : ((const int*)ei)[e];
    return clampi(v, N_NODES);
}
__device__ __forceinline__ int edge_dst(const void* ei, int e) {
    if (e >= N_EDGES) return e - N_EDGES;
    int v = g_is64_ei ? (int)((const long long*)ei)[N_EDGES + e]
                      : ((const int*)ei)[N_EDGES + e];
    return clampi(v, N_NODES);
}
__device__ __forceinline__ int batch_of(const void* b, int n) {
    int v = g_is64_b ? (int)((const long long*)b)[n]
                     : ((const int*)b)[n];
    return clampi(v, N_GRAPHS);
}

// Probe dtypes: view buffers as int32 words (safe: we read only n_elements words,
// which both layouts contain). Non-negative int64 values < 2^31 have all odd-
// indexed words == 0; genuine int32 data has nonzero odd words w.p. ~1.
__global__ void k_detect(const int* __restrict__ eiw, const int* __restrict__ bw) {
    __shared__ int s_ei, s_b;
    int t = threadIdx.x;
    if (t == 0) { s_ei = 0; s_b = 0; }
    __syncthreads();
    int le = 0, lb = 0;
    for (int i = 2 * t + 1; i < 2 * N_EDGES; i += 2048) le |= (eiw[i] != 0);
    for (int i = 2 * t + 1; i < N_NODES;     i += 2048) lb |= (bw[i]  != 0);
    if (le) atomicOr(&s_ei, 1);
    if (lb) atomicOr(&s_b, 1);
    __syncthreads();
    if (t == 0) { g_is64_ei = !s_ei; g_is64_b = !s_b; }
}

// ---------------- helpers ----------------
__device__ __forceinline__ float warp_max(float v) {
    #pragma unroll
    for (int o = 16; o; o >>= 1) v = fmaxf(v, __shfl_xor_sync(0xffffffffu, v, o));
    return v;
}
__device__ __forceinline__ float warp_sum(float v) {
    #pragma unroll
    for (int o = 16; o; o >>= 1) v += __shfl_xor_sync(0xffffffffu, v, o);
    return v;
}
__device__ __forceinline__ unsigned f2tf32(float v) {
    unsigned u;
    asm("cvt.rna.tf32.f32 %0, %1;" : "=r"(u) : "f"(v));
    return u;
}
__device__ __forceinline__ void mma_tf32(float* c, const unsigned* a, const unsigned* b) {
    asm volatile(
        "mma.sync.aligned.m16n8k8.row.col.f32.tf32.tf32.f32 "
        "{%0,%1,%2,%3},{%4,%5,%6,%7},{%8,%9},{%0,%1,%2,%3};"
        : "+f"(c[0]), "+f"(c[1]), "+f"(c[2]), "+f"(c[3])
        : "r"(a[0]), "r"(a[1]), "r"(a[2]), "r"(a[3]), "r"(b[0]), "r"(b[1]));
}
__device__ __forceinline__ void cpa4(uint32_t dst, const float* src, bool pred) {
    int sz = pred ? 4 : 0;
    asm volatile("cp.async.ca.shared.global [%0], [%1], 4, %2;"
                 :: "r"(dst), "l"(src), "r"(sz));
}
__device__ __forceinline__ void cpa16(uint32_t dst, const float* src, bool pred) {
    int sz = pred ? 16 : 0;
    asm volatile("cp.async.cg.shared.global [%0], [%1], 16, %2;"
                 :: "r"(dst), "l"(src), "r"(sz));
}
__device__ __forceinline__ void cpa_commit() {
    asm volatile("cp.async.commit_group;");
}
template <int N>
__device__ __forceinline__ void cpa_wait() {
    asm volatile("cp.async.wait_group %0;" :: "n"(N));
}

// ---------------- setup kernels ----------------
__global__ void k_zero() {
    int i = blockIdx.x * blockDim.x + threadIdx.x;
    if (i < N_NODES) g_deg[i] = 0;
    if (i < N_GRAPHS * OUT_CH) g_pool[i] = 0.f;
    if (i < N_GRAPHS) g_cnt[i] = 0.f;
}

__global__ void k_hist(const void* __restrict__ ei) {
    int e = blockIdx.x * blockDim.x + threadIdx.x;
    if (e >= E_TOT) return;
    atomicAdd(&g_deg[edge_dst(ei, e)], 1);
}

__global__ void k_prefix() {
    __shared__ int part[1024];
    int t = threadIdx.x;
    int s = 0;
    if (t < 1000) {
        #pragma unroll
        for (int i = 0; i < 10; i++) s += g_deg[t * 10 + i];
    }
    part[t] = s;
    __syncthreads();
    for (int off = 1; off < 1024; off <<= 1) {
        int v = (t >= off) ? part[t - off] : 0;
        __syncthreads();
        part[t] += v;
        __syncthreads();
    }
    if (t < 1000) {
        int run = part[t] - s;  // exclusive
        #pragma unroll
        for (int i = 0; i < 10; i++) {
            int d = g_deg[t * 10 + i];
            g_start[t * 10 + i]  = run;
            g_cursor[t * 10 + i] = run;
            run += d;
        }
    }
    if (t == 1023) g_start[N_NODES] = part[1023];
}

__global__ void k_scatter(const void* __restrict__ ei) {
    int e = blockIdx.x * blockDim.x + threadIdx.x;
    if (e >= E_TOT) return;
    int pos = atomicAdd(&g_cursor[edge_dst(ei, e)], 1);
    g_eid[pos] = e;
}

__global__ void k_cnt(const void* __restrict__ batch) {
    int n = blockIdx.x * blockDim.x + threadIdx.x;
    if (n < N_NODES) atomicAdd(&g_cnt[batch_of(batch, n)], 1.0f);
}

// ---------------- tf32 GEMM: C[M,N] = A[M,K] @ B[K,N], 3-stage cp.async ----------------
// which==0: A = x (param, K=4097 odd -> scalar cp.async), C = g_h1
// which==1: A = g_o1 (K=2048 -> vector cp.async),         C = g_h2
#define AS_STRIDE 36
#define BS_STRIDE 132
#define AS_SZ (128 * AS_STRIDE)     // 4608 floats
#define BS_SZ (32 * BS_STRIDE)      // 4224 floats
#define STAGE_SZ (AS_SZ + BS_SZ)    // 8832 floats
#define N_STAGES 3
#define GEMM_SMEM_BYTES (N_STAGES * STAGE_SZ * 4)   // 105984 B

__device__ __forceinline__ void load_tile(const float* __restrict__ A,
                                          const float* __restrict__ Bm,
                                          int M, int N, int K,
                                          int bm, int bn, int kt,
                                          float* As, float* Bs, int tid, bool aVec) {
    if (aVec) {
        // A rows 16B aligned: 4 x 16B per thread (128 rows x 8 float4)
        #pragma unroll
        for (int p = 0; p < 4; p++) {
            int idx = tid + p * 256;
            int r = idx >> 3, c4 = idx & 7;
            int gr = bm + r, gk = kt + c4 * 4;
            bool v = (gr < M) && (gk < K);
            uint32_t d = (uint32_t)__cvta_generic_to_shared(As + r * AS_STRIDE + c4 * 4);
            const float* s = v ? (A + (size_t)gr * K + gk) : A;
            cpa16(d, s, v);
        }
    } else {
        // odd K: 16 x 4B per thread
        #pragma unroll
        for (int p = 0; p < 16; p++) {
            int idx = tid + p * 256;
            int r = idx >> 5, kk = idx & 31;
            int gr = bm + r, gk = kt + kk;
            bool v = (gr < M) && (gk < K);
            uint32_t d = (uint32_t)__cvta_generic_to_shared(As + r * AS_STRIDE + kk);
            const float* s = v ? (A + (size_t)gr * K + gk) : A;
            cpa4(d, s, v);
        }
    }
    // B: 4 x 16B per thread (32 rows x 32 float4)
    #pragma unroll
    for (int p = 0; p < 4; p++) {
        int idx = tid + p * 256;
        int r = idx >> 5, c4 = idx & 31;
        int gk = kt + r;
        bool v = (gk < K);
        uint32_t d = (uint32_t)__cvta_generic_to_shared(Bs + r * BS_STRIDE + c4 * 4);
        const float* s = v ? (Bm + (size_t)gk * N + bn + c4 * 4) : Bm;
        cpa16(d, s, v);
    }
}

__global__ __launch_bounds__(256, 2)
void k_gemm_tf32(int which, const float* __restrict__ Aext,
                 const float* __restrict__ B, int M, int N, int K) {
    extern __shared__ float sm[];

    const float* A = (which == 0) ? Aext : g_o1;
    float* C = (which == 0) ? g_h1 : g_h2;
    const bool aVec = (which != 0);

    int tid = threadIdx.x;
    int wid = tid >> 5, lane = tid & 31;
    int wm = wid & 3, wn = wid >> 2;       // warps 4 x 2 over 128x128
    int bm = blockIdx.x * 128, bn = blockIdx.y * 128;

    float c[2][8][4];
    #pragma unroll
    for (int i = 0; i < 2; i++)
        #pragma unroll
        for (int j = 0; j < 8; j++)
            #pragma unroll
            for (int q = 0; q < 4; q++) c[i][j][q] = 0.f;

    const int nt = (K + 31) / 32;
    // prologue: fill stages 0 and 1
    load_tile(A, B, M, N, K, bm, bn, 0, sm, sm + AS_SZ, tid, aVec);
    cpa_commit();
    if (nt > 1) {
        load_tile(A, B, M, N, K, bm, bn, 32,
                  sm + STAGE_SZ, sm + STAGE_SZ + AS_SZ, tid, aVec);
        cpa_commit();
    }

    for (int t = 0; t < nt; t++) {
        if (t + 1 < nt) cpa_wait<1>(); else cpa_wait<0>();
        __syncthreads();        // all warps past compute(t-1); safe to overwrite (t+2)%3

        if (t + 2 < nt) {
            float* dst = sm + ((t + 2) % N_STAGES) * STAGE_SZ;
            load_tile(A, B, M, N, K, bm, bn, (t + 2) * 32,
                      dst, dst + AS_SZ, tid, aVec);
            cpa_commit();
        }

        float* As32 = sm + (t % N_STAGES) * STAGE_SZ;
        float* Bs32 = As32 + AS_SZ;
        #pragma unroll
        for (int ks = 0; ks < 4; ks++) {
            int k0 = ks * 8;
            unsigned a[2][4], b[8][2];
            #pragma unroll
            for (int mt = 0; mt < 2; mt++) {
                int r0 = wm * 32 + mt * 16 + (lane >> 2);
                int cc0 = k0 + (lane & 3);
                a[mt][0] = f2tf32(As32[r0 * AS_STRIDE + cc0]);
                a[mt][1] = f2tf32(As32[(r0 + 8) * AS_STRIDE + cc0]);
                a[mt][2] = f2tf32(As32[r0 * AS_STRIDE + cc0 + 4]);
                a[mt][3] = f2tf32(As32[(r0 + 8) * AS_STRIDE + cc0 + 4]);
            }
            #pragma unroll
            for (int nt2 = 0; nt2 < 8; nt2++) {
                int kb = k0 + (lane & 3);
                int nb = wn * 64 + nt2 * 8 + (lane >> 2);
                b[nt2][0] = f2tf32(Bs32[kb * BS_STRIDE + nb]);
                b[nt2][1] = f2tf32(Bs32[(kb + 4) * BS_STRIDE + nb]);
            }
            #pragma unroll
            for (int mt = 0; mt < 2; mt++)
                #pragma unroll
                for (int nt2 = 0; nt2 < 8; nt2++)
                    mma_tf32(c[mt][nt2], a[mt], b[nt2]);
        }
    }

    // epilogue
    #pragma unroll
    for (int mt = 0; mt < 2; mt++) {
        int r0 = bm + wm * 32 + mt * 16 + (lane >> 2);
        #pragma unroll
        for (int nt2 = 0; nt2 < 8; nt2++) {
            int cc = bn + wn * 64 + nt2 * 8 + (lane & 3) * 2;
            if (r0 < M) {
                C[(size_t)r0 * N + cc]     = c[mt][nt2][0];
                C[(size_t)r0 * N + cc + 1] = c[mt][nt2][1];
            }
            if (r0 + 8 < M) {
                C[(size_t)(r0 + 8) * N + cc]     = c[mt][nt2][2];
                C[(size_t)(r0 + 8) * N + cc + 1] = c[mt][nt2][3];
            }
        }
    }
}

// ---------------- attention dot products ----------------
__global__ void k_att1(const float* __restrict__ att_s, const float* __restrict__ att_d) {
    int n = blockIdx.x;
    int h = threadIdx.x >> 5, lane = threadIdx.x & 31;
    const float* row = g_h1 + (size_t)n * C1 + h * HID;
    float ss = 0.f, sd = 0.f;
    #pragma unroll 4
    for (int ch = lane; ch < HID; ch += 32) {
        float v = row[ch];
        ss += v * att_s[h * HID + ch];
        sd += v * att_d[h * HID + ch];
    }
    ss = warp_sum(ss);
    sd = warp_sum(sd);
    if (!lane) { g_as1[n * HEADS + h] = ss; g_ad1[n * HEADS + h] = sd; }
}

__global__ void k_att2(const float* __restrict__ att_s, const float* __restrict__ att_d) {
    int wid = threadIdx.x >> 5, lane = threadIdx.x & 31;
    int n = blockIdx.x * 4 + wid;
    if (n >= N_NODES) return;
    const float* row = g_h2 + (size_t)n * OUT_CH;
    float ss = 0.f, sd = 0.f;
    #pragma unroll
    for (int ch = lane; ch < OUT_CH; ch += 32) {
        float v = row[ch];
        ss += v * att_s[ch];
        sd += v * att_d[ch];
    }
    ss = warp_sum(ss);
    sd = warp_sum(sd);
    if (!lane) { g_as2[n] = ss; g_ad2[n] = sd; }
}

// ---------------- layer-1 fused softmax + aggregation (shared-staged) ----------------
__global__ __launch_bounds__(256)
void k_agg1(const void* __restrict__ ei, const float* __restrict__ b1) {
    __shared__ float  sred[8][4];
    __shared__ int    s_src[256];
    __shared__ float4 s_w[256];
    int n = blockIdx.x, tid = threadIdx.x;
    int wid = tid >> 5, lane = tid & 31;
    int s0 = g_start[n], s1 = g_start[n + 1];

    const float4 ad = *(const float4*)(g_ad1 + n * 4);

    // phase A: per-head max over incoming edges
    float m0 = -3.0e38f, m1 = m0, m2 = m0, m3 = m0;
    for (int j = s0 + tid; j < s1; j += 256) {
        int src = edge_src(ei, g_eid[j]);
        const float4 as = *(const float4*)(g_as1 + src * 4);
        float l;
        l = as.x + ad.x; l = l > 0.f ? l : NEG_SLOPE * l; m0 = fmaxf(m0, l);
        l = as.y + ad.y; l = l > 0.f ? l : NEG_SLOPE * l; m1 = fmaxf(m1, l);
        l = as.z + ad.z; l = l > 0.f ? l : NEG_SLOPE * l; m2 = fmaxf(m2, l);
        l = as.w + ad.w; l = l > 0.f ? l : NEG_SLOPE * l; m3 = fmaxf(m3, l);
    }
    m0 = warp_max(m0); m1 = warp_max(m1); m2 = warp_max(m2); m3 = warp_max(m3);
    if (!lane) { sred[wid][0] = m0; sred[wid][1] = m1; sred[wid][2] = m2; sred[wid][3] = m3; }
    __syncthreads();
    float fm0 = sred[0][0], fm1 = sred[0][1], fm2 = sred[0][2], fm3 = sred[0][3];
    #pragma unroll
    for (int w = 1; w < 8; w++) {
        fm0 = fmaxf(fm0, sred[w][0]); fm1 = fmaxf(fm1, sred[w][1]);
        fm2 = fmaxf(fm2, sred[w][2]); fm3 = fmaxf(fm3, sred[w][3]);
    }

    // fused phases B+C, chunked through shared memory.
    // accumulate UNNORMALIZED acc = sum_j w_j * h[src_j]; normalize at the end.
    int ha = tid >> 7;        // head of first channel group (0/1); second = ha+2
    int c0 = tid * 4, c1 = (tid + 256) * 4;
    float4 acc0 = {0.f, 0.f, 0.f, 0.f}, acc1 = {0.f, 0.f, 0.f, 0.f};
    float d0 = 0.f, d1 = 0.f, d2 = 0.f, d3 = 0.f;

    for (int base = s0; base < s1; base += 256) {
        int cnt = min(256, s1 - base);
        __syncthreads();            // protect s_src/s_w from previous chunk readers
        if (tid < cnt) {
            int src = edge_src(ei, g_eid[base + tid]);
            s_src[tid] = src;
            const float4 as = *(const float4*)(g_as1 + src * 4);
            float l; float4 w;
            l = as.x + ad.x; l = l > 0.f ? l : NEG_SLOPE * l; w.x = __expf(l - fm0);
            l = as.y + ad.y; l = l > 0.f ? l : NEG_SLOPE * l; w.y = __expf(l - fm1);
            l = as.z + ad.z; l = l > 0.f ? l : NEG_SLOPE * l; w.z = __expf(l - fm2);
            l = as.w + ad.w; l = l > 0.f ? l : NEG_SLOPE * l; w.w = __expf(l - fm3);
            s_w[tid] = w;
            d0 += w.x; d1 += w.y; d2 += w.z; d3 += w.w;
        }
        __syncthreads();
        #pragma unroll 4
        for (int jj = 0; jj < cnt; jj++) {
            int src = s_src[jj];                      // LDS broadcast
            const float* wv = (const float*)&s_w[jj];
            float wa = wv[ha];
            float wb = wv[ha + 2];
            const float* hrow = g_h1 + (size_t)src * C1;
            float4 v0 = *(const float4*)(hrow + c0);
            float4 v1 = *(const float4*)(hrow + c1);
            acc0.x += wa * v0.x; acc0.y += wa * v0.y; acc0.z += wa * v0.z; acc0.w += wa * v0.w;
            acc1.x += wb * v1.x; acc1.y += wb * v1.y; acc1.z += wb * v1.z; acc1.w += wb * v1.w;
        }
    }

    // block-reduce denominators
    d0 = warp_sum(d0); d1 = warp_sum(d1); d2 = warp_sum(d2); d3 = warp_sum(d3);
    __syncthreads();
    if (!lane) { sred[wid][0] = d0; sred[wid][1] = d1; sred[wid][2] = d2; sred[wid][3] = d3; }
    __syncthreads();
    float fd0 = 0.f, fd1 = 0.f, fd2 = 0.f, fd3 = 0.f;
    #pragma unroll
    for (int w = 0; w < 8; w++) {
        fd0 += sred[w][0]; fd1 += sred[w][1]; fd2 += sred[w][2]; fd3 += sred[w][3];
    }

    float inva = 1.f / ((ha ? fd1 : fd0) + 1e-16f);
    float invb = 1.f / ((ha ? fd3 : fd2) + 1e-16f);
    float* out = g_o1 + (size_t)n * C1;
    float4 o0, o1;
    o0.x = fmaxf(acc0.x * inva + b1[c0 + 0], 0.f);
    o0.y = fmaxf(acc0.y * inva + b1[c0 + 1], 0.f);
    o0.z = fmaxf(acc0.z * inva + b1[c0 + 2], 0.f);
    o0.w = fmaxf(acc0.w * inva + b1[c0 + 3], 0.f);
    o1.x = fmaxf(acc1.x * invb + b1[c1 + 0], 0.f);
    o1.y = fmaxf(acc1.y * invb + b1[c1 + 1], 0.f);
    o1.z = fmaxf(acc1.z * invb + b1[c1 + 2], 0.f);
    o1.w = fmaxf(acc1.w * invb + b1[c1 + 3], 0.f);
    *(float4*)(out + c0) = o0;
    *(float4*)(out + c1) = o1;
}

// ---------------- layer-2 fused softmax + aggregation + pooling ----------------
__global__ __launch_bounds__(256)
void k_agg2(const void* __restrict__ ei, const float* __restrict__ b2,
            const void* __restrict__ batch) {
    __shared__ float sred[8];
    __shared__ int   s_src[256];
    __shared__ float s_wc[256];
    int n = blockIdx.x, tid = threadIdx.x;
    int wid = tid >> 5, lane = tid & 31;
    int s0 = g_start[n], s1 = g_start[n + 1];
    float adn = g_ad2[n];

    float mx = -3.0e38f;
    for (int j = s0 + tid; j < s1; j += 256) {
        int src = edge_src(ei, g_eid[j]);
        float l = g_as2[src] + adn;
        l = l > 0.f ? l : NEG_SLOPE * l;
        mx = fmaxf(mx, l);
    }
    mx = warp_max(mx);
    if (!lane) sred[wid] = mx;
    __syncthreads();
    float fmx = sred[0];
    #pragma unroll
    for (int w = 1; w < 8; w++) fmx = fmaxf(fmx, sred[w]);

    float acc = 0.f, ds = 0.f;
    for (int base = s0; base < s1; base += 256) {
        int cnt = min(256, s1 - base);
        __syncthreads();
        if (tid < cnt) {
            int src = edge_src(ei, g_eid[base + tid]);
            s_src[tid] = src;
            float l = g_as2[src] + adn;
            l = l > 0.f ? l : NEG_SLOPE * l;
            float w = __expf(l - fmx);
            s_wc[tid] = w;
            ds += w;
        }
        __syncthreads();
        #pragma unroll 4
        for (int jj = 0; jj < cnt; jj++) {
            acc += s_wc[jj] * g_h2[(size_t)s_src[jj] * OUT_CH + tid];
        }
    }

    ds = warp_sum(ds);
    __syncthreads();
    if (!lane) sred[wid] = ds;
    __syncthreads();
    float fden = 0.f;
    #pragma unroll
    for (int w = 0; w < 8; w++) fden += sred[w];
    float inv = 1.f / (fden + 1e-16f);

    float val = acc * inv + b2[tid];
    atomicAdd(&g_pool[batch_of(batch, n) * OUT_CH + tid], val);
}

__global__ void k_final(float* __restrict__ out) {
    int i = blockIdx.x * blockDim.x + threadIdx.x;
    if (i < N_GRAPHS * OUT_CH) {
        float c = g_cnt[i >> 8];
        out[i] = g_pool[i] / fmaxf(c, 1.0f);
    }
}

// ---------------- launch ----------------
extern "C" void kernel_launch(void* const* d_in, const int* in_sizes, int n_in,
                              void* d_out, int out_size) {
    const float* x     = (const float*)d_in[0];
    const void*  ei    = d_in[1];
    const void*  batch = d_in[2];
    const float* W1    = (const float*)d_in[3];
    const float* as1   = (const float*)d_in[4];
    const float* ad1   = (const float*)d_in[5];
    const float* b1    = (const float*)d_in[6];
    const float* W2    = (const float*)d_in[7];
    const float* as2   = (const float*)d_in[8];
    const float* ad2   = (const float*)d_in[9];
    const float* b2    = (const float*)d_in[10];
    float* out = (float*)d_out;

    cudaFuncSetAttribute(k_gemm_tf32,
                         cudaFuncAttributeMaxDynamicSharedMemorySize,
                         GEMM_SMEM_BYTES);

    k_detect<<<1, 1024>>>((const int*)ei, (const int*)batch);
    k_zero<<<64, 256>>>();
    k_hist<<<(E_TOT + 255) / 256, 256>>>(ei);
    k_prefix<<<1, 1024>>>();
    k_scatter<<<(E_TOT + 255) / 256, 256>>>(ei);
    k_cnt<<<(N_NODES + 255) / 256, 256>>>(batch);

    dim3 g1((N_NODES + 127) / 128, C1 / 128);
    k_gemm_tf32<<<g1, 256, GEMM_SMEM_BYTES>>>(0, x, W1, N_NODES, C1, IN_CH);

    k_att1<<<N_NODES, 128>>>(as1, ad1);
    k_agg1<<<N_NODES, 256>>>(ei, b1);

    dim3 g2((N_NODES + 127) / 128, OUT_CH / 128);
    k_gemm_tf32<<<g2, 256, GEMM_SMEM_BYTES>>>(1, nullptr, W2, N_NODES, OUT_CH, C1);

    k_att2<<<(N_NODES + 3) / 4, 128>>>(as2, ad2);
    k_agg2<<<N_NODES, 256>>>(ei, b2, batch);

    k_final<<<(N_GRAPHS * OUT_CH + 255) / 256, 256>>>(out);
}